// round 15
// baseline (speedup 1.0000x reference)
#include <cuda_runtime.h>
#include <cuda_bf16.h>
#include <cstdint>

#define HIDDEN   1024
#define CODEBOOK 8192
#define NTOK     8192
#define NSPLIT   4
#define BM       128
#define BN       128
#define BK       32
#define KCHUNKS  (HIDDEN / BK)                  // 32
#define NT_PER_BLOCK ((CODEBOOK / NSPLIT) / BN) // 16
#define NGLOBAL  (NT_PER_BLOCK * KCHUNKS)       // 512 pipeline steps
#define STAGE_BYTES 32768
#define NSTAGE   6
#define SMEM_TOTAL  (NSTAGE * STAGE_BYTES)      // 192 KB

// ---------- device scratch (no runtime allocation allowed) ----------
__device__ int   g_tok_idx[NTOK];
__device__ int   g_n_active;
__device__ float g_tsq[NTOK];
__device__ float g_csq[CODEBOOK];
__device__ float g_partZ[NSPLIT][NTOK];
__device__ float g_partS[NSPLIT][NTOK];
__device__ __nv_bfloat16 g_A1[(size_t)NTOK * HIDDEN];      // hs, compacted
__device__ __nv_bfloat16 g_A2[(size_t)NTOK * HIDDEN];      // tgt, compacted
__device__ __nv_bfloat16 g_Wt[(size_t)CODEBOOK * HIDDEN];  // W transposed (K-major)
__device__ __nv_bfloat16 g_CB[(size_t)CODEBOOK * HIDDEN];  // codebook (K-major)

// ---------- portable PTX helpers (no 'a'-target features) ----------
#define CP_ASYNC16(saddr, gptr) \
    asm volatile("cp.async.cg.shared.global [%0], [%1], 16;" :: "r"(saddr), "l"(gptr))
#define CP_COMMIT()  asm volatile("cp.async.commit_group;" ::: "memory")
#define CP_WAIT2()   asm volatile("cp.async.wait_group 2;" ::: "memory")

static __device__ __forceinline__ void ldsm4(uint32_t* r, uint32_t a) {
    asm volatile("ldmatrix.sync.aligned.m8n8.x4.shared.b16 {%0,%1,%2,%3}, [%4];"
                 : "=r"(r[0]), "=r"(r[1]), "=r"(r[2]), "=r"(r[3]) : "r"(a));
}
static __device__ __forceinline__ void mma16816(float* c, const uint32_t* a, const uint32_t* b) {
    asm volatile(
        "mma.sync.aligned.m16n8k16.row.col.f32.bf16.bf16.f32 "
        "{%0,%1,%2,%3}, {%4,%5,%6,%7}, {%8,%9}, {%0,%1,%2,%3};"
        : "+f"(c[0]), "+f"(c[1]), "+f"(c[2]), "+f"(c[3])
        : "r"(a[0]), "r"(a[1]), "r"(a[2]), "r"(a[3]), "r"(b[0]), "r"(b[1]));
}

// ============================================================
// 1) Compact image-token indices (deterministic, 1 block, 1024 thr).
// ============================================================
__global__ void compact_kernel(const int* __restrict__ tti)
{
    __shared__ int sodd;
    __shared__ int wsum[32];
    const int tid = threadIdx.x;
    if (tid == 0) sodd = 0;
    __syncthreads();
    int acc = 0;
#pragma unroll
    for (int i = tid; i < 4096; i += 1024) acc |= ((const int2*)tti)[i].y;
    if (acc) atomicOr(&sodd, 1);
    __syncthreads();
    const int stride = sodd ? 1 : 2;   // int32 vs int64 layout probe

    const int base = tid * 8;
    int flags[8];
    int c = 0;
#pragma unroll
    for (int i = 0; i < 8; ++i) {
        flags[i] = (tti[(base + i) * stride] == 1);
        c += flags[i];
    }
    const int lane = tid & 31, w = tid >> 5;
    int p = c;
#pragma unroll
    for (int m = 1; m < 32; m <<= 1) {
        int t = __shfl_up_sync(0xffffffffu, p, m);
        if (lane >= m) p += t;
    }
    if (lane == 31) wsum[w] = p;
    __syncthreads();
    if (w == 0) {
        int v = wsum[lane];
#pragma unroll
        for (int m = 1; m < 32; m <<= 1) {
            int t = __shfl_up_sync(0xffffffffu, v, m);
            if (lane >= m) v += t;
        }
        wsum[lane] = v;
    }
    __syncthreads();
    const int wexcl = (w == 0) ? 0 : wsum[w - 1];
    int o = wexcl + p - c;
#pragma unroll
    for (int i = 0; i < 8; ++i)
        if (flags[i]) g_tok_idx[o++] = base + i;
    if (tid == 1023) g_n_active = wexcl + p;
}

// ============================================================
// 2) Fully fused pack:
//    blocks [0,NTOK)                     : A gather+convert (+t_sq)
//    blocks [NTOK, NTOK+CODEBOOK)        : codebook convert (+c_sq)
//    blocks [NTOK+CODEBOOK, +8192)       : W transpose+convert
// ============================================================
__global__ void pack_all_kernel(const float* __restrict__ hs, const float* __restrict__ tgt,
                                const float* __restrict__ cb, const float* __restrict__ W)
{
    __shared__ float wred[8];
    const int tid = threadIdx.x;
    const int k4  = tid * 4;

    if (blockIdx.x < NTOK) {
        const int slot = blockIdx.x;
        __nv_bfloat162* o1 = (__nv_bfloat162*)(g_A1 + (size_t)slot * HIDDEN + k4);
        __nv_bfloat162* o2 = (__nv_bfloat162*)(g_A2 + (size_t)slot * HIDDEN + k4);
        if (slot >= g_n_active) {
            __nv_bfloat162 z = __floats2bfloat162_rn(0.f, 0.f);
            o1[0] = z; o1[1] = z; o2[0] = z; o2[1] = z;
            return;
        }
        size_t r = (size_t)g_tok_idx[slot] * HIDDEN + k4;
        float4 v1 = *(const float4*)(hs + r);
        float4 v2 = *(const float4*)(tgt + r);
        o1[0] = __floats2bfloat162_rn(v1.x, v1.y);
        o1[1] = __floats2bfloat162_rn(v1.z, v1.w);
        o2[0] = __floats2bfloat162_rn(v2.x, v2.y);
        o2[1] = __floats2bfloat162_rn(v2.z, v2.w);
        float sq = v2.x * v2.x + v2.y * v2.y + v2.z * v2.z + v2.w * v2.w;
#pragma unroll
        for (int m = 16; m; m >>= 1) sq += __shfl_xor_sync(0xffffffffu, sq, m);
        if ((tid & 31) == 0) wred[tid >> 5] = sq;
        __syncthreads();
        if (tid == 0) {
            float s = 0.f;
#pragma unroll
            for (int i = 0; i < 8; ++i) s += wred[i];
            g_tsq[slot] = s * (1.0f / HIDDEN);
        }
    } else if (blockIdx.x < NTOK + CODEBOOK) {
        const int c = blockIdx.x - NTOK;
        float4 v = *(const float4*)(cb + (size_t)c * HIDDEN + k4);
        __nv_bfloat162* o = (__nv_bfloat162*)(g_CB + (size_t)c * HIDDEN + k4);
        o[0] = __floats2bfloat162_rn(v.x, v.y);
        o[1] = __floats2bfloat162_rn(v.z, v.w);
        float sq = v.x * v.x + v.y * v.y + v.z * v.z + v.w * v.w;
#pragma unroll
        for (int m = 16; m; m >>= 1) sq += __shfl_xor_sync(0xffffffffu, sq, m);
        if ((tid & 31) == 0) wred[tid >> 5] = sq;
        __syncthreads();
        if (tid == 0) {
            float s = 0.f;
#pragma unroll
            for (int i = 0; i < 8; ++i) s += wred[i];
            g_csq[c] = s;
        }
    } else {
        // W transpose: 32x32 tile per block, flat 256 threads -> (32, 8)
        __shared__ float t[32][33];
        const int bw = blockIdx.x - NTOK - CODEBOOK;      // 0..8191
        const int c0 = (bw & 255) * 32;                   // codeword tile
        const int h0 = (bw >> 8) * 32;                    // hidden tile
        const int tx = tid & 31, ty = tid >> 5;           // (32, 8)
#pragma unroll
        for (int j = 0; j < 4; ++j)
            t[ty + 8 * j][tx] = W[(size_t)(h0 + ty + 8 * j) * CODEBOOK + c0 + tx];
        __syncthreads();
#pragma unroll
        for (int j = 0; j < 4; ++j)
            g_Wt[(size_t)(c0 + ty + 8 * j) * HIDDEN + h0 + tx] =
                __float2bfloat16_rn(t[tx][ty + 8 * j]);
    }
}

// ============================================================
// 3) Fused dual-GEMM (HMMA bf16) + softmax-weighted reduce.
//    6-stage cp.async pipeline, wait_group 2 at pair head
//    (~4-step consumption lead), fragment-batched inner loop.
// ============================================================
__global__ void __launch_bounds__(256, 1)
tdl_hmma(const float* __restrict__ bb)
{
    extern __shared__ char smem[];
    const int tid = threadIdx.x;
    const int n_active = g_n_active;
    const int mtile = blockIdx.x;
    if (mtile * BM >= n_active) return;

    const int wid = tid >> 5, lane = tid & 31;
    const int wm = wid & 3, wn = wid >> 2;

    const __nv_bfloat16* pA1 = g_A1 + (size_t)mtile * BM * HIDDEN;
    const __nv_bfloat16* pA2 = g_A2 + (size_t)mtile * BM * HIDDEN;
    const int nbase = blockIdx.y * (CODEBOOK / NSPLIT);

    const uint32_t sbase = (uint32_t)__cvta_generic_to_shared(smem);

    // ---- cp.async slot precompute: thread -> (row, chunk) of a 128x32 tile ----
    const int rowbase = tid >> 2;                   // 0..63
    const int ch      = tid & 3;                    // 16B chunk in 64B row
    const uint32_t sw = (uint32_t)((ch ^ ((rowbase >> 1) & 3)) << 4);
    const uint32_t soff = (uint32_t)rowbase * 64u + sw;
    const size_t   goff = (size_t)rowbase * HIDDEN + ch * 8;

    // ---- ldmatrix address precompute (XOR-swizzled 64B rows) ----
    uint32_t offA[2]; int xA[2];
#pragma unroll
    for (int mt = 0; mt < 2; ++mt) {
        int r = wm * 32 + mt * 16 + (lane & 7) + ((lane >> 3) & 1) * 8;
        offA[mt] = (uint32_t)r * 64u; xA[mt] = (r >> 1) & 3;
    }
    const int coffA = lane >> 4;
    uint32_t offB[4]; int xB[4];
#pragma unroll
    for (int j = 0; j < 4; ++j) {
        int r = wn * 64 + j * 16 + (lane & 7) + ((lane >> 4) & 1) * 8;
        offB[j] = (uint32_t)r * 64u; xB[j] = (r >> 1) & 3;
    }
    const int coffB = (lane >> 3) & 1;

    float Zr[4], Sr[4];
#pragma unroll
    for (int r = 0; r < 4; ++r) { Zr[r] = 0.f; Sr[r] = 0.f; }

    // issue one pipeline step's copies into explicit stage; ALWAYS commit
    auto issue = [&](int g, int st) {
        if (g < NGLOBAL) {
            const int ntg = g >> 5, kcg = g & 31;
            const __nv_bfloat16* pB1 = g_Wt + (size_t)(nbase + ntg * BN) * HIDDEN;
            const __nv_bfloat16* pB2 = g_CB + (size_t)(nbase + ntg * BN) * HIDDEN;
            const uint32_t s0 = sbase + (uint32_t)st * STAGE_BYTES;
            const size_t k0 = (size_t)kcg * BK;
#pragma unroll
            for (int i = 0; i < 8; ++i) {
                const __nv_bfloat16* mp = (i < 2) ? pA1 : (i < 4) ? pA2 : (i < 6) ? pB1 : pB2;
                const __nv_bfloat16* gp = mp + goff + ((i & 1) ? (size_t)64 * HIDDEN : 0) + k0;
                CP_ASYNC16(s0 + (uint32_t)(i >> 1) * 8192u + soff + ((i & 1) ? 4096u : 0u), gp);
            }
        }
        CP_COMMIT();
    };

    float acc1[64], acc2[64];

    // one compute sub-step over explicit stage
    auto compute = [&](int g, int st) {
        const int kc = g & 31;
        if (kc == 0) {
#pragma unroll
            for (int i = 0; i < 64; ++i) { acc1[i] = 0.f; acc2[i] = 0.f; }
        }
        const uint32_t sb = sbase + (uint32_t)st * STAGE_BYTES;
#pragma unroll
        for (int s = 0; s < 2; ++s) {
            // batch-load A fragments (both GEMMs) + all B1 fragments
            uint32_t a1[2][4], a2[2][4], bf[4][4];
#pragma unroll
            for (int mt = 0; mt < 2; ++mt) {
                uint32_t off = offA[mt] + (uint32_t)(((2 * s + coffA) ^ xA[mt]) << 4);
                ldsm4(a1[mt], sb + off);
                ldsm4(a2[mt], sb + 8192u + off);
            }
#pragma unroll
            for (int j = 0; j < 4; ++j) {
                uint32_t off = offB[j] + (uint32_t)(((2 * s + coffB) ^ xB[j]) << 4);
                ldsm4(bf[j], sb + 16384u + off);
            }
            // GEMM1 mma batch (covers B2 fragment-load latency below)
#pragma unroll
            for (int j = 0; j < 4; ++j)
#pragma unroll
                for (int mt = 0; mt < 2; ++mt) {
                    mma16816(&acc1[mt * 32 + (2 * j) * 4],     a1[mt], bf[j]);
                    mma16816(&acc1[mt * 32 + (2 * j + 1) * 4], a1[mt], bf[j] + 2);
                }
            // batch-load all B2 fragments
#pragma unroll
            for (int j = 0; j < 4; ++j) {
                uint32_t off = offB[j] + (uint32_t)(((2 * s + coffB) ^ xB[j]) << 4);
                ldsm4(bf[j], sb + 24576u + off);
            }
            // GEMM2 mma batch
#pragma unroll
            for (int j = 0; j < 4; ++j)
#pragma unroll
                for (int mt = 0; mt < 2; ++mt) {
                    mma16816(&acc2[mt * 32 + (2 * j) * 4],     a2[mt], bf[j]);
                    mma16816(&acc2[mt * 32 + (2 * j + 1) * 4], a2[mt], bf[j] + 2);
                }
        }

        if (kc == 31) {
            // epilogue: fold 128x128 tile into per-token (Z, S)
            const int n0 = nbase + (g >> 5) * BN;
#pragma unroll
            for (int ntl = 0; ntl < 8; ++ntl) {
                const int c0 = n0 + wn * 64 + ntl * 8 + (lane & 3) * 2;
                const float b0v = __ldg(bb + c0), b1v = __ldg(bb + c0 + 1);
                const float q0 = g_csq[c0], q1 = g_csq[c0 + 1];
#pragma unroll
                for (int mt = 0; mt < 2; ++mt) {
                    const float* a1p = &acc1[mt * 32 + ntl * 4];
                    const float* a2p = &acc2[mt * 32 + ntl * 4];
                    float e0 = __expf(a1p[0] + b0v);
                    float e1 = __expf(a1p[1] + b1v);
                    Zr[mt * 2 + 0] += e0 + e1;
                    Sr[mt * 2 + 0] += e0 * fmaf(-2.f, a2p[0], q0) + e1 * fmaf(-2.f, a2p[1], q1);
                    float e2 = __expf(a1p[2] + b0v);
                    float e3 = __expf(a1p[3] + b1v);
                    Zr[mt * 2 + 1] += e2 + e3;
                    Sr[mt * 2 + 1] += e2 * fmaf(-2.f, a2p[2], q0) + e3 * fmaf(-2.f, a2p[3], q1);
                }
            }
        }
    };

    // prologue: fill 4 of 6 stages
    issue(0, 0); issue(1, 1); issue(2, 2); issue(3, 3);

    // paired steps: wait_group 2 at pair head completes exactly groups
    // {g, g+1} while leaving {g+2, g+3} in flight (~4-step lead).
    // WAR: issue(g+4) writes stage (g-2)%6, whose readers (pair g-2)
    // are covered by this pair's __syncthreads.
    int si = 4, sc = 0;     // rotating stage indices (avoid runtime %6)
#pragma unroll 1
    for (int g = 0; g < NGLOBAL; g += 2) {
        CP_WAIT2();
        __syncthreads();
        issue(g + 4, si); si = (si == NSTAGE - 1) ? 0 : si + 1;
        compute(g, sc);   sc = (sc == NSTAGE - 1) ? 0 : sc + 1;
        issue(g + 5, si); si = (si == NSTAGE - 1) ? 0 : si + 1;
        compute(g + 1, sc); sc = (sc == NSTAGE - 1) ? 0 : sc + 1;
    }

    // ---- reduce across the 4 lanes sharing each row ----
#pragma unroll
    for (int r = 0; r < 4; ++r) {
        Zr[r] += __shfl_xor_sync(0xffffffffu, Zr[r], 1);
        Zr[r] += __shfl_xor_sync(0xffffffffu, Zr[r], 2);
        Sr[r] += __shfl_xor_sync(0xffffffffu, Sr[r], 1);
        Sr[r] += __shfl_xor_sync(0xffffffffu, Sr[r], 2);
    }
    __syncthreads();                    // smem stage area free for reuse
    float* zbuf = (float*)smem;         // [2][128]
    float* sbuf = zbuf + 256;           // [2][128]
    if ((lane & 3) == 0) {
        int gg = lane >> 2;
#pragma unroll
        for (int r = 0; r < 4; ++r) {
            int row = wm * 32 + (r >> 1) * 16 + (r & 1) * 8 + gg;
            zbuf[wn * 128 + row] = Zr[r];
            sbuf[wn * 128 + row] = Sr[r];
        }
    }
    __syncthreads();
    if (tid < 128) {
        int slot = mtile * BM + tid;
        if (slot < n_active) {
            g_partZ[blockIdx.y][slot] = zbuf[tid] + zbuf[128 + tid];
            g_partS[blockIdx.y][slot] = sbuf[tid] + sbuf[128 + tid];
        }
    }
}

// ============================================================
// 4) Final deterministic reduction.
// ============================================================
__global__ void reduce_kernel(float* __restrict__ out)
{
    __shared__ float sm[256];
    const int tid = threadIdx.x;
    const int n = g_n_active;
    float s = 0.f;
    for (int i = tid; i < n; i += 256) {
        float Z = 0.f, S = 0.f;
#pragma unroll
        for (int p = 0; p < NSPLIT; ++p) { Z += g_partZ[p][i]; S += g_partS[p][i]; }
        s += g_tsq[i] + S / (Z * (float)HIDDEN);
    }
    sm[tid] = s;
    __syncthreads();
    for (int m = 128; m; m >>= 1) {
        if (tid < m) sm[tid] += sm[tid + m];
        __syncthreads();
    }
    if (tid == 0) out[0] = sm[0] * 0.1f;
}

// ============================================================
extern "C" void kernel_launch(void* const* d_in, const int* in_sizes, int n_in,
                              void* d_out, int out_size)
{
    (void)in_sizes; (void)n_in; (void)out_size;
    const float* hs  = (const float*)d_in[0];
    const int*   tti = (const int*)  d_in[1];
    const float* tgt = (const float*)d_in[2];
    const float* cb  = (const float*)d_in[3];
    const float* W   = (const float*)d_in[4];
    const float* b   = (const float*)d_in[5];
    float* out = (float*)d_out;

    cudaFuncSetAttribute(tdl_hmma, cudaFuncAttributeMaxDynamicSharedMemorySize, SMEM_TOTAL);

    compact_kernel<<<1, 1024>>>(tti);
    pack_all_kernel<<<NTOK + CODEBOOK + 8192, 256>>>(hs, tgt, cb, W);

    dim3 grid(NTOK / BM, NSPLIT);
    tdl_hmma<<<grid, 256, SMEM_TOTAL>>>(b);
    reduce_kernel<<<1, 256>>>(out);
}